// round 4
// baseline (speedup 1.0000x reference)
#include <cuda_runtime.h>
#include <cuda_bf16.h>
#include <math.h>
#include <stdint.h>

// Problem constants (fixed shapes)
#define B_DIM 8192
#define D_DIM 512
#define H_DIM 4
#define M_DIM 128
#define W_DIM 64
#define N_DIM (H_DIM * W_DIM)   // 256
#define EPS 1e-6f

// Scratch for tanh(hidden @ W_key + b_key): [B, 256] fp32 = 8 MB
__device__ float g_key[(size_t)B_DIM * N_DIM];

// ---------------------------------------------------------------------------
// Kernel A: tiled fp32 GEMM with packed fma.rn.f32x2 (Blackwell FFMA2).
// key = tanh(hidden[B,512] @ W_key[512,256] + b_key)
// BM=128, BN=128, BK=16, 256 threads, 8(row)x8(col) tile as 8x4 f32x2 pairs,
// double-buffered smem. Grid = (2, 64) = 128 blocks -> exactly 1 wave.
// ---------------------------------------------------------------------------
#define GBM 128
#define GBN 128
#define GBK 16

__global__ __launch_bounds__(256)
void key_gemm_kernel(const float* __restrict__ A,      // hidden [B, 512]
                     const float* __restrict__ Wk,     // [512, 256]
                     const float* __restrict__ bk,     // [256]
                     float* __restrict__ out)          // g_key [B, 256]
{
    __shared__ float As[2][GBK][GBM + 4];
    __shared__ float Bs[2][GBK][GBN];

    const int tid = threadIdx.x;
    const int tx = tid & 15;        // 0..15 -> cols (8 each)
    const int ty = tid >> 4;        // 0..15 -> rows (8 each)

    const int row0 = blockIdx.y * GBM;
    const int col0 = blockIdx.x * GBN;

    const int f0 = tid, f1 = tid + 256;
    const int ar0 = f0 >> 2, ac0 = (f0 & 3) << 2;
    const int ar1 = f1 >> 2, ac1 = (f1 & 3) << 2;
    const int br0 = f0 >> 5, bc0 = (f0 & 31) << 2;
    const int br1 = f1 >> 5, bc1 = (f1 & 31) << 2;

    // packed accumulators: acc2[i][j] holds cols {2j, 2j+1} of row i
    unsigned long long acc2[8][4];
    #pragma unroll
    for (int i = 0; i < 8; i++)
        #pragma unroll
        for (int j = 0; j < 4; j++) acc2[i][j] = 0ull;

    // ---- prologue: load tile 0 into buffer 0 ----
    {
        float4 a0 = *(const float4*)&A[(size_t)(row0 + ar0) * D_DIM + ac0];
        float4 a1 = *(const float4*)&A[(size_t)(row0 + ar1) * D_DIM + ac1];
        float4 b0 = *(const float4*)&Wk[(size_t)br0 * N_DIM + col0 + bc0];
        float4 b1 = *(const float4*)&Wk[(size_t)br1 * N_DIM + col0 + bc1];
        As[0][ac0 + 0][ar0] = a0.x; As[0][ac0 + 1][ar0] = a0.y;
        As[0][ac0 + 2][ar0] = a0.z; As[0][ac0 + 3][ar0] = a0.w;
        As[0][ac1 + 0][ar1] = a1.x; As[0][ac1 + 1][ar1] = a1.y;
        As[0][ac1 + 2][ar1] = a1.z; As[0][ac1 + 3][ar1] = a1.w;
        *(float4*)&Bs[0][br0][bc0] = b0;
        *(float4*)&Bs[0][br1][bc1] = b1;
    }
    __syncthreads();

    const int NSTEP = D_DIM / GBK;   // 32
    #pragma unroll 1
    for (int s = 0; s < NSTEP; s++) {
        const int cbuf = s & 1;
        const int nbuf = cbuf ^ 1;
        const int k0n  = (s + 1) * GBK;

        float4 pa0, pa1, pb0, pb1;
        if (s + 1 < NSTEP) {
            pa0 = *(const float4*)&A[(size_t)(row0 + ar0) * D_DIM + k0n + ac0];
            pa1 = *(const float4*)&A[(size_t)(row0 + ar1) * D_DIM + k0n + ac1];
            pb0 = *(const float4*)&Wk[(size_t)(k0n + br0) * N_DIM + col0 + bc0];
            pb1 = *(const float4*)&Wk[(size_t)(k0n + br1) * N_DIM + col0 + bc1];
        }

        #pragma unroll
        for (int k = 0; k < GBK; k++) {
            // A fragment: 8 scalars, duplicated into both f32x2 halves
            float a[8];
            #pragma unroll
            for (int i = 0; i < 8; i += 4) {
                float4 av = *(const float4*)&As[cbuf][k][ty * 8 + i];
                a[i + 0] = av.x; a[i + 1] = av.y; a[i + 2] = av.z; a[i + 3] = av.w;
            }
            unsigned long long a2[8];
            #pragma unroll
            for (int i = 0; i < 8; i++) {
                unsigned int ai = __float_as_uint(a[i]);
                asm("mov.b64 %0, {%1, %1};" : "=l"(a2[i]) : "r"(ai));
            }
            // B fragment: 4 packed pairs (adjacent cols), 16B-aligned smem reads
            unsigned long long b2[4];
            {
                const ulonglong2* bp = (const ulonglong2*)&Bs[cbuf][k][tx * 8];
                ulonglong2 v0 = bp[0], v1 = bp[1];
                b2[0] = v0.x; b2[1] = v0.y; b2[2] = v1.x; b2[3] = v1.y;
            }
            #pragma unroll
            for (int i = 0; i < 8; i++)
                #pragma unroll
                for (int j = 0; j < 4; j++)
                    asm("fma.rn.f32x2 %0, %1, %2, %0;"
                        : "+l"(acc2[i][j]) : "l"(a2[i]), "l"(b2[j]));
        }

        if (s + 1 < NSTEP) {
            As[nbuf][ac0 + 0][ar0] = pa0.x; As[nbuf][ac0 + 1][ar0] = pa0.y;
            As[nbuf][ac0 + 2][ar0] = pa0.z; As[nbuf][ac0 + 3][ar0] = pa0.w;
            As[nbuf][ac1 + 0][ar1] = pa1.x; As[nbuf][ac1 + 1][ar1] = pa1.y;
            As[nbuf][ac1 + 2][ar1] = pa1.z; As[nbuf][ac1 + 3][ar1] = pa1.w;
            *(float4*)&Bs[nbuf][br0][bc0] = pb0;
            *(float4*)&Bs[nbuf][br1][bc1] = pb1;
        }
        __syncthreads();
    }

    // epilogue: unpack, tanh(acc + bias), vectorized store
    float bia[8];
    #pragma unroll
    for (int j = 0; j < 8; j++) bia[j] = bk[col0 + tx * 8 + j];

    #pragma unroll
    for (int i = 0; i < 8; i++) {
        int r = row0 + ty * 8 + i;
        float c[8];
        #pragma unroll
        for (int j = 0; j < 4; j++) {
            unsigned int lo, hi;
            asm("mov.b64 {%0, %1}, %2;" : "=r"(lo), "=r"(hi) : "l"(acc2[i][j]));
            c[2 * j + 0] = __uint_as_float(lo);
            c[2 * j + 1] = __uint_as_float(hi);
        }
        float4 o0, o1;
        o0.x = tanhf(c[0] + bia[0]);
        o0.y = tanhf(c[1] + bia[1]);
        o0.z = tanhf(c[2] + bia[2]);
        o0.w = tanhf(c[3] + bia[3]);
        o1.x = tanhf(c[4] + bia[4]);
        o1.y = tanhf(c[5] + bia[5]);
        o1.z = tanhf(c[6] + bia[6]);
        o1.w = tanhf(c[7] + bia[7]);
        float* op = &out[(size_t)r * N_DIM + col0 + tx * 8];
        *(float4*)op       = o0;
        *(float4*)(op + 4) = o1;
    }
}

// ---------------------------------------------------------------------------
// Kernel B: persistent attention blocks with cp.async double buffering.
// Grid = 444 (148 SMs x 3 CTAs), each block strides over batch rows,
// prefetching memory[b+stride] while computing on memory[b].
// ---------------------------------------------------------------------------
#define MEM_PITCH 68            // 64 + 4 pad floats; conflict-free LDS.128
#define ATT_GRID 444
#define TILE_FLOATS (M_DIM * MEM_PITCH)            // 8704 floats per buffer
#define ATT_DYN_SMEM (2 * TILE_FLOATS * 4)         // 69632 bytes

__device__ __forceinline__ void issue_tile(const float* __restrict__ memory,
                                           int b, float* dst, int tid)
{
    const float4* gp = (const float4*)&memory[(size_t)b * M_DIM * W_DIM];
    #pragma unroll
    for (int i = 0; i < 16; i++) {
        int f  = tid + i * M_DIM;        // 0..2047 float4 index
        int m  = f >> 4;                 // row
        int w4 = f & 15;                 // float4 within row
        unsigned int daddr =
            (unsigned int)__cvta_generic_to_shared(&dst[m * MEM_PITCH + w4 * 4]);
        asm volatile("cp.async.cg.shared.global [%0], [%1], 16;\n"
                     :: "r"(daddr), "l"(gp + f));
    }
    asm volatile("cp.async.commit_group;\n");
}

__global__ __launch_bounds__(M_DIM)
void attn_kernel(const float* __restrict__ hidden,   // [B, 512]
                 const float* __restrict__ memory,   // [B, 128, 64]
                 const float* __restrict__ Wb,       // [512, 4]
                 const float* __restrict__ bb,       // [4]
                 const float* __restrict__ key,      // g_key [B, 256]
                 float* __restrict__ out)            // [B, 4, 128]
{
    extern __shared__ float dynsm[];
    float* mem_buf[2] = { dynsm, dynsm + TILE_FLOATS };

    __shared__ float key_s[N_DIM];
    __shared__ float u2_s[H_DIM];
    __shared__ float beta_s[H_DIM];
    __shared__ float red_max[H_DIM][4];
    __shared__ float red_sum[H_DIM][4];

    const int tid  = threadIdx.x;
    const int lane = tid & 31;
    const int warp = tid >> 5;   // 0..3 == head id
    const int m    = tid;

    // prologue: start first tile
    issue_tile(memory, blockIdx.x, mem_buf[0], tid);

    int it = 0;
    for (int b = blockIdx.x; b < B_DIM; b += gridDim.x, it++) {
        float* cb = mem_buf[it & 1];
        const int bn = b + gridDim.x;

        // start key-row load early (independent of cp.async)
        float2 kv = __ldg((const float2*)&key[(size_t)b * N_DIM] + tid);

        if (bn < B_DIM) {
            issue_tile(memory, bn, mem_buf[(it & 1) ^ 1], tid);
            asm volatile("cp.async.wait_group 1;\n");
        } else {
            asm volatile("cp.async.wait_group 0;\n");
        }
        *((float2*)key_s + tid) = kv;
        __syncthreads();    // tile + key_s visible

        // warp h: u2[h] = sum(key[h]^2) + EPS
        {
            float t0 = key_s[warp * W_DIM + lane];
            float t1 = key_s[warp * W_DIM + 32 + lane];
            float ss = t0 * t0 + t1 * t1;
            #pragma unroll
            for (int off = 16; off > 0; off >>= 1)
                ss += __shfl_xor_sync(0xffffffffu, ss, off);
            if (lane == 0) u2_s[warp] = ss + EPS;
        }

        // warp h: beta[h] = softplus(hidden[b] . Wb[:,h] + bb[h])
        {
            const float* hrow = &hidden[(size_t)b * D_DIM];
            float s = 0.f;
            #pragma unroll 4
            for (int d = lane; d < D_DIM; d += 32)
                s += hrow[d] * Wb[d * H_DIM + warp];
            #pragma unroll
            for (int off = 16; off > 0; off >>= 1)
                s += __shfl_xor_sync(0xffffffffu, s, off);
            if (lane == 0) {
                float x = s + bb[warp];
                beta_s[warp] = (x > 15.f) ? x : log1pf(expf(x));
            }
        }
        __syncthreads();

        // thread m: own row from smem, v2 + 4 head dots
        float v2 = 0.f;
        float num[H_DIM] = {0.f, 0.f, 0.f, 0.f};
        #pragma unroll
        for (int i = 0; i < W_DIM / 4; i++) {
            float4 v = *(const float4*)&cb[m * MEM_PITCH + i * 4];
            v2 += v.x * v.x + v.y * v.y + v.z * v.z + v.w * v.w;
            #pragma unroll
            for (int h = 0; h < H_DIM; h++) {
                const float* ks = &key_s[h * W_DIM + i * 4];
                num[h] += ks[0] * v.x + ks[1] * v.y + ks[2] * v.z + ks[3] * v.w;
            }
        }
        v2 += EPS;

        // logits
        float l[H_DIM];
        #pragma unroll
        for (int h = 0; h < H_DIM; h++) {
            float den = sqrtf(u2_s[h] * v2);
            float kk  = num[h] / (den + EPS);
            l[h] = kk * beta_s[h];
        }

        // block softmax over 128 threads, per head
        #pragma unroll
        for (int h = 0; h < H_DIM; h++) {
            float t = l[h];
            #pragma unroll
            for (int off = 16; off > 0; off >>= 1)
                t = fmaxf(t, __shfl_xor_sync(0xffffffffu, t, off));
            if (lane == 0) red_max[h][warp] = t;
        }
        __syncthreads();
        float mx[H_DIM];
        #pragma unroll
        for (int h = 0; h < H_DIM; h++)
            mx[h] = fmaxf(fmaxf(red_max[h][0], red_max[h][1]),
                          fmaxf(red_max[h][2], red_max[h][3]));

        float e[H_DIM];
        #pragma unroll
        for (int h = 0; h < H_DIM; h++) {
            e[h] = __expf(l[h] - mx[h]);
            float t = e[h];
            #pragma unroll
            for (int off = 16; off > 0; off >>= 1)
                t += __shfl_xor_sync(0xffffffffu, t, off);
            if (lane == 0) red_sum[h][warp] = t;
        }
        __syncthreads();

        #pragma unroll
        for (int h = 0; h < H_DIM; h++) {
            float sm = red_sum[h][0] + red_sum[h][1] + red_sum[h][2] + red_sum[h][3];
            out[((size_t)b * H_DIM + h) * M_DIM + m] = e[h] / sm;
        }

        __syncthreads();   // all reads of cb done before it's overwritten next iter
    }
}

// ---------------------------------------------------------------------------
// Launch
// ---------------------------------------------------------------------------
extern "C" void kernel_launch(void* const* d_in, const int* in_sizes, int n_in,
                              void* d_out, int out_size)
{
    const float* hidden = (const float*)d_in[0];   // [8192, 512]
    const float* memory = (const float*)d_in[1];   // [8192, 128, 64]
    const float* W_key  = (const float*)d_in[2];   // [512, 256]
    const float* b_key  = (const float*)d_in[3];   // [256]
    const float* W_beta = (const float*)d_in[4];   // [512, 4]
    const float* b_beta = (const float*)d_in[5];   // [4]
    float* out = (float*)d_out;                    // [8192, 4, 128]

    float* keybuf;
    cudaGetSymbolAddress((void**)&keybuf, g_key);

    cudaFuncSetAttribute(attn_kernel,
                         cudaFuncAttributeMaxDynamicSharedMemorySize,
                         ATT_DYN_SMEM);

    dim3 gridA(N_DIM / GBN, B_DIM / GBM);   // (2, 64) = 128 blocks
    key_gemm_kernel<<<gridA, 256>>>(hidden, W_key, b_key, keybuf);

    attn_kernel<<<ATT_GRID, M_DIM, ATT_DYN_SMEM>>>(hidden, memory, W_beta,
                                                   b_beta, keybuf, out);
}

// round 5
// speedup vs baseline: 1.2825x; 1.2825x over previous
#include <cuda_runtime.h>
#include <cuda_bf16.h>
#include <math.h>
#include <stdint.h>

// Problem constants (fixed shapes)
#define B_DIM 8192
#define D_DIM 512
#define H_DIM 4
#define M_DIM 128
#define W_DIM 64
#define N_DIM (H_DIM * W_DIM)   // 256
#define EPS 1e-6f

// Scratch: tanh(hidden @ W_key + b_key): [B, 256] fp32 = 8 MB
__device__ float g_key[(size_t)B_DIM * N_DIM];
// Scratch: u2[b][h] = sum_w key^2 (no EPS)
__device__ float g_u2[(size_t)B_DIM * H_DIM];

// ---------------------------------------------------------------------------
// Kernel A: tiled fp32 GEMM  key = tanh(hidden[B,512] @ W_key[512,256] + b_key)
// BM=128, BN=128, BK=16, 256 threads, 8x8 register tile, double-buffered smem.
// Grid = (2, 64) = 128 blocks -> exactly 1 wave.
// Epilogue also reduces u2[b][h] = sum over the 64 cols of each head
// (8-lane butterfly; this block's tx-halves each cover one full head).
// ---------------------------------------------------------------------------
#define GBM 128
#define GBN 128
#define GBK 16

__global__ __launch_bounds__(256)
void key_gemm_kernel(const float* __restrict__ A,      // hidden [B, 512]
                     const float* __restrict__ Wk,     // [512, 256]
                     const float* __restrict__ bk,     // [256]
                     float* __restrict__ out,          // g_key [B, 256]
                     float* __restrict__ u2out)        // g_u2  [B, 4]
{
    __shared__ float As[2][GBK][GBM + 4];
    __shared__ float Bs[2][GBK][GBN];

    const int tid = threadIdx.x;
    const int tx = tid & 15;        // 0..15 -> cols (8 each)
    const int ty = tid >> 4;        // 0..15 -> rows (8 each)

    const int row0 = blockIdx.y * GBM;
    const int col0 = blockIdx.x * GBN;

    const int f0 = tid, f1 = tid + 256;
    const int ar0 = f0 >> 2, ac0 = (f0 & 3) << 2;
    const int ar1 = f1 >> 2, ac1 = (f1 & 3) << 2;
    const int br0 = f0 >> 5, bc0 = (f0 & 31) << 2;
    const int br1 = f1 >> 5, bc1 = (f1 & 31) << 2;

    float acc[8][8] = {};

    // ---- prologue: load tile 0 into buffer 0 ----
    {
        float4 a0 = *(const float4*)&A[(size_t)(row0 + ar0) * D_DIM + ac0];
        float4 a1 = *(const float4*)&A[(size_t)(row0 + ar1) * D_DIM + ac1];
        float4 b0 = *(const float4*)&Wk[(size_t)br0 * N_DIM + col0 + bc0];
        float4 b1 = *(const float4*)&Wk[(size_t)br1 * N_DIM + col0 + bc1];
        As[0][ac0 + 0][ar0] = a0.x; As[0][ac0 + 1][ar0] = a0.y;
        As[0][ac0 + 2][ar0] = a0.z; As[0][ac0 + 3][ar0] = a0.w;
        As[0][ac1 + 0][ar1] = a1.x; As[0][ac1 + 1][ar1] = a1.y;
        As[0][ac1 + 2][ar1] = a1.z; As[0][ac1 + 3][ar1] = a1.w;
        *(float4*)&Bs[0][br0][bc0] = b0;
        *(float4*)&Bs[0][br1][bc1] = b1;
    }
    __syncthreads();

    const int NSTEP = D_DIM / GBK;   // 32
    #pragma unroll 1
    for (int s = 0; s < NSTEP; s++) {
        const int cbuf = s & 1;
        const int nbuf = cbuf ^ 1;
        const int k0n  = (s + 1) * GBK;

        float4 pa0, pa1, pb0, pb1;
        if (s + 1 < NSTEP) {
            pa0 = *(const float4*)&A[(size_t)(row0 + ar0) * D_DIM + k0n + ac0];
            pa1 = *(const float4*)&A[(size_t)(row0 + ar1) * D_DIM + k0n + ac1];
            pb0 = *(const float4*)&Wk[(size_t)(k0n + br0) * N_DIM + col0 + bc0];
            pb1 = *(const float4*)&Wk[(size_t)(k0n + br1) * N_DIM + col0 + bc1];
        }

        #pragma unroll
        for (int k = 0; k < GBK; k++) {
            float a[8], b[8];
            #pragma unroll
            for (int i = 0; i < 8; i += 4) {
                float4 av = *(const float4*)&As[cbuf][k][ty * 8 + i];
                a[i + 0] = av.x; a[i + 1] = av.y; a[i + 2] = av.z; a[i + 3] = av.w;
            }
            #pragma unroll
            for (int j = 0; j < 8; j += 4) {
                float4 bv = *(const float4*)&Bs[cbuf][k][tx * 8 + j];
                b[j + 0] = bv.x; b[j + 1] = bv.y; b[j + 2] = bv.z; b[j + 3] = bv.w;
            }
            #pragma unroll
            for (int i = 0; i < 8; i++)
                #pragma unroll
                for (int j = 0; j < 8; j++)
                    acc[i][j] += a[i] * b[j];
        }

        if (s + 1 < NSTEP) {
            As[nbuf][ac0 + 0][ar0] = pa0.x; As[nbuf][ac0 + 1][ar0] = pa0.y;
            As[nbuf][ac0 + 2][ar0] = pa0.z; As[nbuf][ac0 + 3][ar0] = pa0.w;
            As[nbuf][ac1 + 0][ar1] = pa1.x; As[nbuf][ac1 + 1][ar1] = pa1.y;
            As[nbuf][ac1 + 2][ar1] = pa1.z; As[nbuf][ac1 + 3][ar1] = pa1.w;
            *(float4*)&Bs[nbuf][br0][bc0] = pb0;
            *(float4*)&Bs[nbuf][br1][bc1] = pb1;
        }
        __syncthreads();
    }

    // epilogue: tanh(acc + bias), store, and u2 reduce
    float bia[8];
    #pragma unroll
    for (int j = 0; j < 8; j++) bia[j] = bk[col0 + tx * 8 + j];

    // This thread's 8 cols lie entirely inside head hloc = (col0 + tx*8)/64:
    // head = blockIdx.x*2 + (tx>>3)
    const int head = blockIdx.x * 2 + (tx >> 3);

    #pragma unroll
    for (int i = 0; i < 8; i++) {
        int r = row0 + ty * 8 + i;
        float4 o0, o1;
        o0.x = tanhf(acc[i][0] + bia[0]);
        o0.y = tanhf(acc[i][1] + bia[1]);
        o0.z = tanhf(acc[i][2] + bia[2]);
        o0.w = tanhf(acc[i][3] + bia[3]);
        o1.x = tanhf(acc[i][4] + bia[4]);
        o1.y = tanhf(acc[i][5] + bia[5]);
        o1.z = tanhf(acc[i][6] + bia[6]);
        o1.w = tanhf(acc[i][7] + bia[7]);
        float* op = &out[(size_t)r * N_DIM + col0 + tx * 8];
        *(float4*)op       = o0;
        *(float4*)(op + 4) = o1;

        // partial u2 over this thread's 8 cols
        float p = o0.x * o0.x + o0.y * o0.y + o0.z * o0.z + o0.w * o0.w
                + o1.x * o1.x + o1.y * o1.y + o1.z * o1.z + o1.w * o1.w;
        // butterfly over the 8 lanes sharing (ty, head): lane-xor 1,2,4
        p += __shfl_xor_sync(0xffffffffu, p, 1);
        p += __shfl_xor_sync(0xffffffffu, p, 2);
        p += __shfl_xor_sync(0xffffffffu, p, 4);
        if ((tx & 7) == 0)
            u2out[(size_t)r * H_DIM + head] = p;
    }
}

// ---------------------------------------------------------------------------
// Kernel B: one-shot attention, 1 block (128 threads) per batch row.
// memory[b] staged via cp.async.cg into a 32KB XOR-swizzled smem tile
// (pitch 64, no padding); beta + key/u2 loads overlap the in-flight DMA.
// ---------------------------------------------------------------------------
#define ATT_SMEM (M_DIM * 16 * 16)     // 2048 float4 = 32768 bytes

__global__ __launch_bounds__(M_DIM)
void attn_kernel(const float* __restrict__ hidden,   // [B, 512]
                 const float* __restrict__ memory,   // [B, 128, 64]
                 const float* __restrict__ Wb,       // [512, 4]
                 const float* __restrict__ bb,       // [4]
                 const float* __restrict__ key,      // g_key [B, 256]
                 const float* __restrict__ u2in,     // g_u2 [B, 4]
                 float* __restrict__ out)            // [B, 4, 128]
{
    extern __shared__ float4 tile[];                 // [128 rows][16 f4] swizzled

    __shared__ float key_s[N_DIM];
    __shared__ float u2_s[H_DIM];
    __shared__ float beta_s[H_DIM];
    __shared__ float red_max[H_DIM][4];
    __shared__ float red_sum[H_DIM][4];

    const int b    = blockIdx.x;
    const int tid  = threadIdx.x;
    const int lane = tid & 31;
    const int warp = tid >> 5;   // 0..3 == head id
    const int m    = tid;

    // ---- fire the tile DMA (cp.async.cg, L1 bypass, swizzled dest) ----
    {
        const float4* gp = (const float4*)&memory[(size_t)b * M_DIM * W_DIM];
        #pragma unroll
        for (int i = 0; i < 16; i++) {
            int f  = tid + i * M_DIM;        // 0..2047
            int mr = f >> 4;                 // row
            int w4 = f & 15;                 // float4 within row
            int sl = mr * 16 + (w4 ^ (mr & 15));
            unsigned int daddr = (unsigned int)__cvta_generic_to_shared(&tile[sl]);
            asm volatile("cp.async.cg.shared.global [%0], [%1], 16;\n"
                         :: "r"(daddr), "l"(gp + f));
        }
        asm volatile("cp.async.commit_group;\n");
    }

    // ---- overlap with the DMA: key row, u2, beta ----
    {
        const float2* kp = (const float2*)&key[(size_t)b * N_DIM];
        *((float2*)key_s + tid) = kp[tid];
    }
    if (tid < H_DIM)
        u2_s[tid] = u2in[(size_t)b * H_DIM + tid] + EPS;

    // warp h: beta[h] = softplus(hidden[b] . Wb[:,h] + bb[h])  (L2-resident)
    {
        const float* hrow = &hidden[(size_t)b * D_DIM];
        float s = 0.f;
        #pragma unroll 4
        for (int d = lane; d < D_DIM; d += 32)
            s += hrow[d] * Wb[d * H_DIM + warp];
        #pragma unroll
        for (int off = 16; off > 0; off >>= 1)
            s += __shfl_xor_sync(0xffffffffu, s, off);
        if (lane == 0) {
            float x = s + bb[warp];
            beta_s[warp] = (x > 15.f) ? x : log1pf(expf(x));
        }
    }

    asm volatile("cp.async.wait_group 0;\n");
    __syncthreads();   // tile + key_s + u2_s + beta_s visible

    // ---- thread m: own row from swizzled smem, v2 + 4 head dots ----
    float v2 = 0.f;
    float num[H_DIM] = {0.f, 0.f, 0.f, 0.f};
    #pragma unroll
    for (int i = 0; i < 16; i++) {
        float4 v = tile[m * 16 + (i ^ (m & 15))];
        v2 += v.x * v.x + v.y * v.y + v.z * v.z + v.w * v.w;
        const float* ks = &key_s[i * 4];   // wait: need per-head offset
        (void)ks;
        #pragma unroll
        for (int h = 0; h < H_DIM; h++) {
            const float* kh = &key_s[h * W_DIM + i * 4];
            num[h] += kh[0] * v.x + kh[1] * v.y + kh[2] * v.z + kh[3] * v.w;
        }
    }
    v2 += EPS;

    // logits
    float l[H_DIM];
    #pragma unroll
    for (int h = 0; h < H_DIM; h++) {
        float den = sqrtf(u2_s[h] * v2);
        float kk  = num[h] / (den + EPS);
        l[h] = kk * beta_s[h];
    }

    // block softmax over 128 threads, per head
    #pragma unroll
    for (int h = 0; h < H_DIM; h++) {
        float t = l[h];
        #pragma unroll
        for (int off = 16; off > 0; off >>= 1)
            t = fmaxf(t, __shfl_xor_sync(0xffffffffu, t, off));
        if (lane == 0) red_max[h][warp] = t;
    }
    __syncthreads();
    float mx[H_DIM];
    #pragma unroll
    for (int h = 0; h < H_DIM; h++)
        mx[h] = fmaxf(fmaxf(red_max[h][0], red_max[h][1]),
                      fmaxf(red_max[h][2], red_max[h][3]));

    float e[H_DIM];
    #pragma unroll
    for (int h = 0; h < H_DIM; h++) {
        e[h] = __expf(l[h] - mx[h]);
        float t = e[h];
        #pragma unroll
        for (int off = 16; off > 0; off >>= 1)
            t += __shfl_xor_sync(0xffffffffu, t, off);
        if (lane == 0) red_sum[h][warp] = t;
    }
    __syncthreads();

    #pragma unroll
    for (int h = 0; h < H_DIM; h++) {
        float sm = red_sum[h][0] + red_sum[h][1] + red_sum[h][2] + red_sum[h][3];
        out[((size_t)b * H_DIM + h) * M_DIM + m] = e[h] / sm;
    }
}

// ---------------------------------------------------------------------------
// Launch
// ---------------------------------------------------------------------------
extern "C" void kernel_launch(void* const* d_in, const int* in_sizes, int n_in,
                              void* d_out, int out_size)
{
    const float* hidden = (const float*)d_in[0];   // [8192, 512]
    const float* memory = (const float*)d_in[1];   // [8192, 128, 64]
    const float* W_key  = (const float*)d_in[2];   // [512, 256]
    const float* b_key  = (const float*)d_in[3];   // [256]
    const float* W_beta = (const float*)d_in[4];   // [512, 4]
    const float* b_beta = (const float*)d_in[5];   // [4]
    float* out = (float*)d_out;                    // [8192, 4, 128]

    float* keybuf;
    float* u2buf;
    cudaGetSymbolAddress((void**)&keybuf, g_key);
    cudaGetSymbolAddress((void**)&u2buf, g_u2);

    dim3 gridA(N_DIM / GBN, B_DIM / GBM);   // (2, 64) = 128 blocks
    key_gemm_kernel<<<gridA, 256>>>(hidden, W_key, b_key, keybuf, u2buf);

    attn_kernel<<<B_DIM, M_DIM, ATT_SMEM>>>(hidden, memory, W_beta, b_beta,
                                            keybuf, u2buf, out);
}

// round 7
// speedup vs baseline: 1.3573x; 1.0584x over previous
#include <cuda_runtime.h>
#include <cuda_bf16.h>
#include <math.h>
#include <stdint.h>

// Problem constants (fixed shapes)
#define B_DIM 8192
#define D_DIM 512
#define H_DIM 4
#define M_DIM 128
#define W_DIM 64
#define N_DIM (H_DIM * W_DIM)   // 256
#define EPS 1e-6f

// Scratch: tanh(hidden @ W_key + b_key): [B, 256] fp32 = 8 MB
__device__ float g_key[(size_t)B_DIM * N_DIM];

// ---------------------------------------------------------------------------
// Kernel A: tiled fp32 GEMM  key = tanh(hidden[B,512] @ W_key[512,256] + b_key)
// BM=128, BN=128, BK=16, 256 threads, 8x8 register tile, double-buffered smem.
// Grid = (2, 64) = 128 blocks -> exactly 1 wave.   (round-3 proven version)
// ---------------------------------------------------------------------------
#define GBM 128
#define GBN 128
#define GBK 16

__global__ __launch_bounds__(256)
void key_gemm_kernel(const float* __restrict__ A,      // hidden [B, 512]
                     const float* __restrict__ Wk,     // [512, 256]
                     const float* __restrict__ bk,     // [256]
                     float* __restrict__ out)          // g_key [B, 256]
{
    __shared__ float As[2][GBK][GBM + 4];
    __shared__ float Bs[2][GBK][GBN];

    const int tid = threadIdx.x;
    const int tx = tid & 15;
    const int ty = tid >> 4;

    const int row0 = blockIdx.y * GBM;
    const int col0 = blockIdx.x * GBN;

    const int f0 = tid, f1 = tid + 256;
    const int ar0 = f0 >> 2, ac0 = (f0 & 3) << 2;
    const int ar1 = f1 >> 2, ac1 = (f1 & 3) << 2;
    const int br0 = f0 >> 5, bc0 = (f0 & 31) << 2;
    const int br1 = f1 >> 5, bc1 = (f1 & 31) << 2;

    float acc[8][8] = {};

    {
        float4 a0 = *(const float4*)&A[(size_t)(row0 + ar0) * D_DIM + ac0];
        float4 a1 = *(const float4*)&A[(size_t)(row0 + ar1) * D_DIM + ac1];
        float4 b0 = *(const float4*)&Wk[(size_t)br0 * N_DIM + col0 + bc0];
        float4 b1 = *(const float4*)&Wk[(size_t)br1 * N_DIM + col0 + bc1];
        As[0][ac0 + 0][ar0] = a0.x; As[0][ac0 + 1][ar0] = a0.y;
        As[0][ac0 + 2][ar0] = a0.z; As[0][ac0 + 3][ar0] = a0.w;
        As[0][ac1 + 0][ar1] = a1.x; As[0][ac1 + 1][ar1] = a1.y;
        As[0][ac1 + 2][ar1] = a1.z; As[0][ac1 + 3][ar1] = a1.w;
        *(float4*)&Bs[0][br0][bc0] = b0;
        *(float4*)&Bs[0][br1][bc1] = b1;
    }
    __syncthreads();

    const int NSTEP = D_DIM / GBK;   // 32
    #pragma unroll 1
    for (int s = 0; s < NSTEP; s++) {
        const int cbuf = s & 1;
        const int nbuf = cbuf ^ 1;
        const int k0n  = (s + 1) * GBK;

        float4 pa0, pa1, pb0, pb1;
        if (s + 1 < NSTEP) {
            pa0 = *(const float4*)&A[(size_t)(row0 + ar0) * D_DIM + k0n + ac0];
            pa1 = *(const float4*)&A[(size_t)(row0 + ar1) * D_DIM + k0n + ac1];
            pb0 = *(const float4*)&Wk[(size_t)(k0n + br0) * N_DIM + col0 + bc0];
            pb1 = *(const float4*)&Wk[(size_t)(k0n + br1) * N_DIM + col0 + bc1];
        }

        #pragma unroll
        for (int k = 0; k < GBK; k++) {
            float a[8], b[8];
            #pragma unroll
            for (int i = 0; i < 8; i += 4) {
                float4 av = *(const float4*)&As[cbuf][k][ty * 8 + i];
                a[i + 0] = av.x; a[i + 1] = av.y; a[i + 2] = av.z; a[i + 3] = av.w;
            }
            #pragma unroll
            for (int j = 0; j < 8; j += 4) {
                float4 bv = *(const float4*)&Bs[cbuf][k][tx * 8 + j];
                b[j + 0] = bv.x; b[j + 1] = bv.y; b[j + 2] = bv.z; b[j + 3] = bv.w;
            }
            #pragma unroll
            for (int i = 0; i < 8; i++)
                #pragma unroll
                for (int j = 0; j < 8; j++)
                    acc[i][j] += a[i] * b[j];
        }

        if (s + 1 < NSTEP) {
            As[nbuf][ac0 + 0][ar0] = pa0.x; As[nbuf][ac0 + 1][ar0] = pa0.y;
            As[nbuf][ac0 + 2][ar0] = pa0.z; As[nbuf][ac0 + 3][ar0] = pa0.w;
            As[nbuf][ac1 + 0][ar1] = pa1.x; As[nbuf][ac1 + 1][ar1] = pa1.y;
            As[nbuf][ac1 + 2][ar1] = pa1.z; As[nbuf][ac1 + 3][ar1] = pa1.w;
            *(float4*)&Bs[nbuf][br0][bc0] = pb0;
            *(float4*)&Bs[nbuf][br1][bc1] = pb1;
        }
        __syncthreads();
    }

    float bia[8];
    #pragma unroll
    for (int j = 0; j < 8; j++) bia[j] = bk[col0 + tx * 8 + j];

    #pragma unroll
    for (int i = 0; i < 8; i++) {
        int r = row0 + ty * 8 + i;
        float4 o0, o1;
        o0.x = tanhf(acc[i][0] + bia[0]);
        o0.y = tanhf(acc[i][1] + bia[1]);
        o0.z = tanhf(acc[i][2] + bia[2]);
        o0.w = tanhf(acc[i][3] + bia[3]);
        o1.x = tanhf(acc[i][4] + bia[4]);
        o1.y = tanhf(acc[i][5] + bia[5]);
        o1.z = tanhf(acc[i][6] + bia[6]);
        o1.w = tanhf(acc[i][7] + bia[7]);
        float* op = &out[(size_t)r * N_DIM + col0 + tx * 8];
        *(float4*)op       = o0;
        *(float4*)(op + 4) = o1;
    }
}

// ---------------------------------------------------------------------------
// Kernel B: one-shot attention, 256 threads per batch row (split-row).
// Thread (m = tid>>1, half = tid&1) processes 32 of 64 row elements.
// Tile staged via cp.async.cg into XOR-swizzled smem; beta/key/u2 overlap
// the DMA. No softmax max-stabilization (logits provably small).
// ---------------------------------------------------------------------------
#define ATT_THREADS 256
#define ATT_SMEM (M_DIM * 16 * 16)     // 2048 float4 = 32768 bytes

__global__ __launch_bounds__(ATT_THREADS, 6)
void attn_kernel(const float* __restrict__ hidden,   // [B, 512]
                 const float* __restrict__ memory,   // [B, 128, 64]
                 const float* __restrict__ Wb,       // [512, 4]
                 const float* __restrict__ bb,       // [4]
                 const float* __restrict__ key,      // g_key [B, 256]
                 float* __restrict__ out)            // [B, 4, 128]
{
    extern __shared__ float4 tile[];                 // [128 rows][16 f4] swizzled

    __shared__ float4 key4[N_DIM / 4];               // 64 float4 = key row
    __shared__ float  u2_s[H_DIM];
    __shared__ float  beta_s[H_DIM];
    __shared__ float4 bpart[4];                      // per-warp beta partials
    __shared__ float4 red_s[8];                      // per-warp e-sums (4 heads)

    const int b    = blockIdx.x;
    const int tid  = threadIdx.x;
    const int lane = tid & 31;
    const int warp = tid >> 5;   // 0..7
    const int m    = tid >> 1;   // memory row
    const int half = tid & 1;    // which 32-element half

    // ---- fire the tile DMA (cp.async.cg, L1 bypass, swizzled dest) ----
    {
        const float4* gp = (const float4*)&memory[(size_t)b * M_DIM * W_DIM];
        #pragma unroll
        for (int i = 0; i < 8; i++) {
            int f  = tid + i * ATT_THREADS;  // 0..2047
            int mr = f >> 4;
            int w4 = f & 15;
            int sl = mr * 16 + (w4 ^ (mr & 15));
            unsigned int daddr = (unsigned int)__cvta_generic_to_shared(&tile[sl]);
            asm volatile("cp.async.cg.shared.global [%0], [%1], 16;\n"
                         :: "r"(daddr), "l"(gp + f));
        }
        asm volatile("cp.async.commit_group;\n");
    }

    // ---- overlap with the DMA: beta partials (warps 0-3), key (4-5), u2 (6-7)
    const float4* keyrow4 = (const float4*)&key[(size_t)b * N_DIM];

    if (warp < 4) {
        // beta partial over d in [warp*128, warp*128+128), vectorized
        const float4* h4 = (const float4*)&hidden[(size_t)b * D_DIM];
        float4 hv = h4[warp * 32 + lane];
        const float4* wb4 = (const float4*)Wb;       // Wb[d] is a float4 (4 heads)
        int d0 = warp * 128 + lane * 4;
        float4 w0 = wb4[d0 + 0], w1 = wb4[d0 + 1], w2 = wb4[d0 + 2], w3 = wb4[d0 + 3];
        float4 p;
        p.x = hv.x * w0.x + hv.y * w1.x + hv.z * w2.x + hv.w * w3.x;
        p.y = hv.x * w0.y + hv.y * w1.y + hv.z * w2.y + hv.w * w3.y;
        p.z = hv.x * w0.z + hv.y * w1.z + hv.z * w2.z + hv.w * w3.z;
        p.w = hv.x * w0.w + hv.y * w1.w + hv.z * w2.w + hv.w * w3.w;
        #pragma unroll
        for (int off = 16; off > 0; off >>= 1) {
            p.x += __shfl_xor_sync(0xffffffffu, p.x, off);
            p.y += __shfl_xor_sync(0xffffffffu, p.y, off);
            p.z += __shfl_xor_sync(0xffffffffu, p.z, off);
            p.w += __shfl_xor_sync(0xffffffffu, p.w, off);
        }
        if (lane == 0) bpart[warp] = p;
    } else if (warp < 6) {
        // key row into smem: 64 float4, warps 4-5
        int idx = (warp - 4) * 32 + lane;
        key4[idx] = keyrow4[idx];
    } else {
        // u2: warp 6 -> heads 0,1 ; warp 7 -> heads 2,3
        int idx = (warp - 6) * 32 + lane;            // float4 index into key row
        float4 v = keyrow4[idx];
        float ss = v.x * v.x + v.y * v.y + v.z * v.z + v.w * v.w;
        #pragma unroll
        for (int off = 8; off > 0; off >>= 1)        // reduce within 16-lane halves
            ss += __shfl_xor_sync(0xffffffffu, ss, off);
        if ((lane & 15) == 0)
            u2_s[(warp - 6) * 2 + (lane >> 4)] = ss + EPS;
    }

    asm volatile("cp.async.wait_group 0;\n");
    __syncthreads();   // barrier 1: tile, key4, u2_s, bpart visible

    // beta finalize (overlaps the dot loop of other threads)
    if (tid < H_DIM) {
        float s = ((const float*)&bpart[0])[tid] + ((const float*)&bpart[1])[tid]
                + ((const float*)&bpart[2])[tid] + ((const float*)&bpart[3])[tid]
                + bb[tid];
        beta_s[tid] = (s > 15.f) ? s : __logf(1.f + __expf(s));
    }

    // ---- dot loop: this thread's 32 elements (half of row m) ----
    float v2 = 0.f;
    float num[H_DIM] = {0.f, 0.f, 0.f, 0.f};
    #pragma unroll
    for (int i = 0; i < 8; i++) {
        int w4l = half * 8 + i;                      // float4 index within row
        float4 v = tile[m * 16 + (w4l ^ (m & 15))];
        v2 += v.x * v.x + v.y * v.y + v.z * v.z + v.w * v.w;
        #pragma unroll
        for (int h = 0; h < H_DIM; h++) {
            float4 kh = key4[h * 16 + w4l];
            num[h] += kh.x * v.x + kh.y * v.y + kh.z * v.z + kh.w * v.w;
        }
    }
    // combine the two halves of row m (lanes 2m, 2m+1 adjacent)
    #pragma unroll
    for (int h = 0; h < H_DIM; h++)
        num[h] += __shfl_xor_sync(0xffffffffu, num[h], 1);
    v2 += __shfl_xor_sync(0xffffffffu, v2, 1);
    v2 += EPS;

    __syncthreads();   // barrier 2: beta_s ready (and red_s free)

    // logits -> exp (no max subtraction: |l| <~ 3)
    float e[H_DIM];
    #pragma unroll
    for (int h = 0; h < H_DIM; h++) {
        float den = sqrtf(u2_s[h] * v2);
        float kk  = num[h] / (den + EPS);
        e[h] = __expf(kk * beta_s[h]);
    }

    // per-warp sum (each m counted twice -> 2x sum), then cross-warp via smem
    {
        float4 es = make_float4(e[0], e[1], e[2], e[3]);
        #pragma unroll
        for (int off = 16; off > 0; off >>= 1) {
            es.x += __shfl_xor_sync(0xffffffffu, es.x, off);
            es.y += __shfl_xor_sync(0xffffffffu, es.y, off);
            es.z += __shfl_xor_sync(0xffffffffu, es.z, off);
            es.w += __shfl_xor_sync(0xffffffffu, es.w, off);
        }
        if (lane == 0) red_s[warp] = es;
    }
    __syncthreads();   // barrier 3

    float4 t0 = red_s[0], t1 = red_s[1], t2 = red_s[2], t3 = red_s[3];
    float4 t4 = red_s[4], t5 = red_s[5], t6 = red_s[6], t7 = red_s[7];
    float sm[H_DIM];
    sm[0] = 0.5f * (t0.x + t1.x + t2.x + t3.x + t4.x + t5.x + t6.x + t7.x);
    sm[1] = 0.5f * (t0.y + t1.y + t2.y + t3.y + t4.y + t5.y + t6.y + t7.y);
    sm[2] = 0.5f * (t0.z + t1.z + t2.z + t3.z + t4.z + t5.z + t6.z + t7.z);
    sm[3] = 0.5f * (t0.w + t1.w + t2.w + t3.w + t4.w + t5.w + t6.w + t7.w);

    // each thread writes 2 heads: half0 -> h 0,1 ; half1 -> h 2,3
    #pragma unroll
    for (int j = 0; j < 2; j++) {
        int h = half * 2 + j;
        out[((size_t)b * H_DIM + h) * M_DIM + m] = e[h] / sm[h];
    }
}

// ---------------------------------------------------------------------------
// Launch
// ---------------------------------------------------------------------------
extern "C" void kernel_launch(void* const* d_in, const int* in_sizes, int n_in,
                              void* d_out, int out_size)
{
    const float* hidden = (const float*)d_in[0];   // [8192, 512]
    const float* memory = (const float*)d_in[1];   // [8192, 128, 64]
    const float* W_key  = (const float*)d_in[2];   // [512, 256]
    const float* b_key  = (const float*)d_in[3];   // [256]
    const float* W_beta = (const float*)d_in[4];   // [512, 4]
    const float* b_beta = (const float*)d_in[5];   // [4]
    float* out = (float*)d_out;                    // [8192, 4, 128]

    float* keybuf;
    cudaGetSymbolAddress((void**)&keybuf, g_key);

    dim3 gridA(N_DIM / GBN, B_DIM / GBM);   // (2, 64) = 128 blocks
    key_gemm_kernel<<<gridA, 256>>>(hidden, W_key, b_key, keybuf);

    attn_kernel<<<B_DIM, ATT_THREADS, ATT_SMEM>>>(hidden, memory, W_beta,
                                                  b_beta, keybuf, out);
}

// round 8
// speedup vs baseline: 1.6887x; 1.2441x over previous
#include <cuda_runtime.h>
#include <cuda_bf16.h>
#include <mma.h>
#include <math.h>
#include <stdint.h>

using namespace nvcuda;

// Problem constants (fixed shapes)
#define B_DIM 8192
#define D_DIM 512
#define H_DIM 4
#define M_DIM 128
#define W_DIM 64
#define N_DIM (H_DIM * W_DIM)   // 256
#define EPS 1e-6f

// Scratch
__device__ float g_key[(size_t)B_DIM * N_DIM];                    // 8 MB
__device__ __nv_bfloat16 g_ah[(size_t)B_DIM * D_DIM];             // hidden hi
__device__ __nv_bfloat16 g_al[(size_t)B_DIM * D_DIM];             // hidden lo
__device__ __nv_bfloat16 g_wh[(size_t)D_DIM * N_DIM];             // W_key hi
__device__ __nv_bfloat16 g_wl[(size_t)D_DIM * N_DIM];             // W_key lo

// ---------------------------------------------------------------------------
// Kernel 0: split fp32 -> bf16 (hi, lo) for hidden and W_key.
// ---------------------------------------------------------------------------
#define HID4 ((B_DIM * D_DIM) / 4)      // 1,048,576 float4
#define WK4  ((D_DIM * N_DIM) / 4)      // 32,768 float4

__device__ __forceinline__ void split_store(float4 v,
                                            __nv_bfloat16* hi,
                                            __nv_bfloat16* lo,
                                            size_t e)   // element index (mult of 4)
{
    float x[4] = {v.x, v.y, v.z, v.w};
    __align__(8) __nv_bfloat16 h[4], l[4];
    #pragma unroll
    for (int j = 0; j < 4; j++) {
        h[j] = __float2bfloat16(x[j]);
        l[j] = __float2bfloat16(x[j] - __bfloat162float(h[j]));
    }
    *(uint2*)(hi + e) = *(uint2*)h;
    *(uint2*)(lo + e) = *(uint2*)l;
}

__global__ __launch_bounds__(256)
void split_kernel(const float* __restrict__ hidden,
                  const float* __restrict__ Wk)
{
    int i = blockIdx.x * 256 + threadIdx.x;
    if (i < HID4) {
        float4 v = ((const float4*)hidden)[i];
        split_store(v, g_ah, g_al, (size_t)i * 4);
    } else {
        int j = i - HID4;
        if (j < WK4) {
            float4 v = ((const float4*)Wk)[j];
            split_store(v, g_wh, g_wl, (size_t)j * 4);
        }
    }
}

// ---------------------------------------------------------------------------
// Kernel A: bf16 split-GEMM on tensor cores (wmma m16n16k16).
// key = tanh( (Ah+Al) @ (Wh+Wl) + b )  ~=  tanh( Ah@Wh + Ah@Wl + Al@Wh + b )
// Block tile 128x128, 8 warps (4 row-groups x 2 col-groups), warp tile 32x64.
// K-tile 32. Grid = (2, 64) = 128 blocks.
// ---------------------------------------------------------------------------
#define KB 32
#define APITCH 40     // bf16 elems per A smem row (80 B, ldmatrix conflict-free)
#define BPITCH 136    // bf16 elems per B smem row (272 B)

// smem layout (bytes):
//  Ah: 128*40*2 = 10240   @ 0
//  Al: 10240              @ 10240
//  Bh: 32*136*2 = 8704    @ 20480
//  Bl: 8704               @ 29184
//  total 37888; epilogue reuses the same buffer (8 warps * 16*24 fp32 = 12288 B)
#define SM_AH 0
#define SM_AL 10240
#define SM_BH 20480
#define SM_BL 29184
#define SM_TOTAL 37888
#define EPI_PITCH 24

__global__ __launch_bounds__(256)
void key_gemm_kernel(const float* __restrict__ bk,     // [256]
                     float* __restrict__ out)          // g_key [B, 256]
{
    __shared__ __align__(16) unsigned char smem_raw[SM_TOTAL];
    __nv_bfloat16* Ah = (__nv_bfloat16*)(smem_raw + SM_AH);
    __nv_bfloat16* Al = (__nv_bfloat16*)(smem_raw + SM_AL);
    __nv_bfloat16* Bh = (__nv_bfloat16*)(smem_raw + SM_BH);
    __nv_bfloat16* Bl = (__nv_bfloat16*)(smem_raw + SM_BL);

    const int tid  = threadIdx.x;
    const int warp = tid >> 5;
    const int lane = tid & 31;
    const int wr   = warp >> 1;          // 0..3 row group (32 rows each)
    const int wc   = warp & 1;           // 0..1 col group (64 cols each)

    const int row0 = blockIdx.y * 128;
    const int col0 = blockIdx.x * 128;

    // A tile load map: 128x32 bf16 = 512 uint4 -> 2 per thread
    const int aF0 = tid, aF1 = tid + 256;
    const int ar0 = aF0 >> 2, ac0 = (aF0 & 3) * 8;
    const int ar1 = aF1 >> 2, ac1 = (aF1 & 3) * 8;
    // B tile: 32x128 bf16 = 512 uint4 -> 2 per thread
    const int br0 = aF0 >> 4, bc0 = (aF0 & 15) * 8;
    const int br1 = aF1 >> 4, bc1 = (aF1 & 15) * 8;

    wmma::fragment<wmma::accumulator, 16, 16, 16, float> acc[2][4];
    #pragma unroll
    for (int i = 0; i < 2; i++)
        #pragma unroll
        for (int j = 0; j < 4; j++)
            wmma::fill_fragment(acc[i][j], 0.0f);

    #pragma unroll 1
    for (int k0 = 0; k0 < D_DIM; k0 += KB) {
        // stage tiles (bf16 already; uint4 = 8 elems)
        *(uint4*)&Ah[ar0 * APITCH + ac0] =
            *(const uint4*)&g_ah[(size_t)(row0 + ar0) * D_DIM + k0 + ac0];
        *(uint4*)&Ah[ar1 * APITCH + ac1] =
            *(const uint4*)&g_ah[(size_t)(row0 + ar1) * D_DIM + k0 + ac1];
        *(uint4*)&Al[ar0 * APITCH + ac0] =
            *(const uint4*)&g_al[(size_t)(row0 + ar0) * D_DIM + k0 + ac0];
        *(uint4*)&Al[ar1 * APITCH + ac1] =
            *(const uint4*)&g_al[(size_t)(row0 + ar1) * D_DIM + k0 + ac1];
        *(uint4*)&Bh[br0 * BPITCH + bc0] =
            *(const uint4*)&g_wh[(size_t)(k0 + br0) * N_DIM + col0 + bc0];
        *(uint4*)&Bh[br1 * BPITCH + bc1] =
            *(const uint4*)&g_wh[(size_t)(k0 + br1) * N_DIM + col0 + bc1];
        *(uint4*)&Bl[br0 * BPITCH + bc0] =
            *(const uint4*)&g_wl[(size_t)(k0 + br0) * N_DIM + col0 + bc0];
        *(uint4*)&Bl[br1 * BPITCH + bc1] =
            *(const uint4*)&g_wl[(size_t)(k0 + br1) * N_DIM + col0 + bc1];
        __syncthreads();

        #pragma unroll
        for (int kk = 0; kk < KB; kk += 16) {
            wmma::fragment<wmma::matrix_a, 16, 16, 16, __nv_bfloat16, wmma::row_major> fah[2], fal[2];
            wmma::fragment<wmma::matrix_b, 16, 16, 16, __nv_bfloat16, wmma::row_major> fbh[4], fbl[4];
            #pragma unroll
            for (int i = 0; i < 2; i++) {
                const __nv_bfloat16* ap = &Ah[(wr * 32 + i * 16) * APITCH + kk];
                const __nv_bfloat16* lp = &Al[(wr * 32 + i * 16) * APITCH + kk];
                wmma::load_matrix_sync(fah[i], ap, APITCH);
                wmma::load_matrix_sync(fal[i], lp, APITCH);
            }
            #pragma unroll
            for (int j = 0; j < 4; j++) {
                const __nv_bfloat16* bp = &Bh[kk * BPITCH + wc * 64 + j * 16];
                const __nv_bfloat16* lp = &Bl[kk * BPITCH + wc * 64 + j * 16];
                wmma::load_matrix_sync(fbh[j], bp, BPITCH);
                wmma::load_matrix_sync(fbl[j], lp, BPITCH);
            }
            #pragma unroll
            for (int i = 0; i < 2; i++)
                #pragma unroll
                for (int j = 0; j < 4; j++) {
                    wmma::mma_sync(acc[i][j], fah[i], fbh[j], acc[i][j]);
                    wmma::mma_sync(acc[i][j], fah[i], fbl[j], acc[i][j]);
                    wmma::mma_sync(acc[i][j], fal[i], fbh[j], acc[i][j]);
                }
        }
        __syncthreads();
    }

    // ---- epilogue: per-warp smem staging -> tanh(+bias) -> coalesced store
    float* scr = (float*)(smem_raw) + warp * 16 * EPI_PITCH;   // 1536 B/warp
    const int er = lane >> 1;            // 0..15 row within tile
    const int ec = (lane & 1) * 8;       // col half (8 floats)

    #pragma unroll
    for (int i = 0; i < 2; i++) {
        #pragma unroll
        for (int j = 0; j < 4; j++) {
            wmma::store_matrix_sync(scr, acc[i][j], EPI_PITCH, wmma::mem_row_major);
            __syncwarp();
            const int gr = row0 + wr * 32 + i * 16 + er;
            const int gc = col0 + wc * 64 + j * 16 + ec;
            float4 c0 = *(float4*)&scr[er * EPI_PITCH + ec];
            float4 c1 = *(float4*)&scr[er * EPI_PITCH + ec + 4];
            float4 b0 = __ldg((const float4*)&bk[gc]);
            float4 b1 = __ldg((const float4*)&bk[gc + 4]);
            float4 o0, o1;
            o0.x = tanhf(c0.x + b0.x); o0.y = tanhf(c0.y + b0.y);
            o0.z = tanhf(c0.z + b0.z); o0.w = tanhf(c0.w + b0.w);
            o1.x = tanhf(c1.x + b1.x); o1.y = tanhf(c1.y + b1.y);
            o1.z = tanhf(c1.z + b1.z); o1.w = tanhf(c1.w + b1.w);
            *(float4*)&out[(size_t)gr * N_DIM + gc]     = o0;
            *(float4*)&out[(size_t)gr * N_DIM + gc + 4] = o1;
            __syncwarp();
        }
    }
}

// ---------------------------------------------------------------------------
// Kernel B: one-shot attention, 256 threads per batch row (round-7 proven).
// ---------------------------------------------------------------------------
#define ATT_THREADS 256
#define ATT_SMEM (M_DIM * 16 * 16)     // 2048 float4 = 32768 bytes

__global__ __launch_bounds__(ATT_THREADS, 6)
void attn_kernel(const float* __restrict__ hidden,   // [B, 512]
                 const float* __restrict__ memory,   // [B, 128, 64]
                 const float* __restrict__ Wb,       // [512, 4]
                 const float* __restrict__ bb,       // [4]
                 const float* __restrict__ key,      // g_key [B, 256]
                 float* __restrict__ out)            // [B, 4, 128]
{
    extern __shared__ float4 tile[];                 // [128 rows][16 f4] swizzled

    __shared__ float4 key4[N_DIM / 4];
    __shared__ float  u2_s[H_DIM];
    __shared__ float  beta_s[H_DIM];
    __shared__ float4 bpart[4];
    __shared__ float4 red_s[8];

    const int b    = blockIdx.x;
    const int tid  = threadIdx.x;
    const int lane = tid & 31;
    const int warp = tid >> 5;
    const int m    = tid >> 1;
    const int half = tid & 1;

    {
        const float4* gp = (const float4*)&memory[(size_t)b * M_DIM * W_DIM];
        #pragma unroll
        for (int i = 0; i < 8; i++) {
            int f  = tid + i * ATT_THREADS;
            int mr = f >> 4;
            int w4 = f & 15;
            int sl = mr * 16 + (w4 ^ (mr & 15));
            unsigned int daddr = (unsigned int)__cvta_generic_to_shared(&tile[sl]);
            asm volatile("cp.async.cg.shared.global [%0], [%1], 16;\n"
                         :: "r"(daddr), "l"(gp + f));
        }
        asm volatile("cp.async.commit_group;\n");
    }

    const float4* keyrow4 = (const float4*)&key[(size_t)b * N_DIM];

    if (warp < 4) {
        const float4* h4 = (const float4*)&hidden[(size_t)b * D_DIM];
        float4 hv = h4[warp * 32 + lane];
        const float4* wb4 = (const float4*)Wb;
        int d0 = warp * 128 + lane * 4;
        float4 w0 = wb4[d0 + 0], w1 = wb4[d0 + 1], w2 = wb4[d0 + 2], w3 = wb4[d0 + 3];
        float4 p;
        p.x = hv.x * w0.x + hv.y * w1.x + hv.z * w2.x + hv.w * w3.x;
        p.y = hv.x * w0.y + hv.y * w1.y + hv.z * w2.y + hv.w * w3.y;
        p.z = hv.x * w0.z + hv.y * w1.z + hv.z * w2.z + hv.w * w3.z;
        p.w = hv.x * w0.w + hv.y * w1.w + hv.z * w2.w + hv.w * w3.w;
        #pragma unroll
        for (int off = 16; off > 0; off >>= 1) {
            p.x += __shfl_xor_sync(0xffffffffu, p.x, off);
            p.y += __shfl_xor_sync(0xffffffffu, p.y, off);
            p.z += __shfl_xor_sync(0xffffffffu, p.z, off);
            p.w += __shfl_xor_sync(0xffffffffu, p.w, off);
        }
        if (lane == 0) bpart[warp] = p;
    } else if (warp < 6) {
        int idx = (warp - 4) * 32 + lane;
        key4[idx] = keyrow4[idx];
    } else {
        int idx = (warp - 6) * 32 + lane;
        float4 v = keyrow4[idx];
        float ss = v.x * v.x + v.y * v.y + v.z * v.z + v.w * v.w;
        #pragma unroll
        for (int off = 8; off > 0; off >>= 1)
            ss += __shfl_xor_sync(0xffffffffu, ss, off);
        if ((lane & 15) == 0)
            u2_s[(warp - 6) * 2 + (lane >> 4)] = ss + EPS;
    }

    asm volatile("cp.async.wait_group 0;\n");
    __syncthreads();

    if (tid < H_DIM) {
        float s = ((const float*)&bpart[0])[tid] + ((const float*)&bpart[1])[tid]
                + ((const float*)&bpart[2])[tid] + ((const float*)&bpart[3])[tid]
                + bb[tid];
        beta_s[tid] = (s > 15.f) ? s : __logf(1.f + __expf(s));
    }

    float v2 = 0.f;
    float num[H_DIM] = {0.f, 0.f, 0.f, 0.f};
    #pragma unroll
    for (int i = 0; i < 8; i++) {
        int w4l = half * 8 + i;
        float4 v = tile[m * 16 + (w4l ^ (m & 15))];
        v2 += v.x * v.x + v.y * v.y + v.z * v.z + v.w * v.w;
        #pragma unroll
        for (int h = 0; h < H_DIM; h++) {
            float4 kh = key4[h * 16 + w4l];
            num[h] += kh.x * v.x + kh.y * v.y + kh.z * v.z + kh.w * v.w;
        }
    }
    #pragma unroll
    for (int h = 0; h < H_DIM; h++)
        num[h] += __shfl_xor_sync(0xffffffffu, num[h], 1);
    v2 += __shfl_xor_sync(0xffffffffu, v2, 1);
    v2 += EPS;

    __syncthreads();

    float e[H_DIM];
    #pragma unroll
    for (int h = 0; h < H_DIM; h++) {
        float den = sqrtf(u2_s[h] * v2);
        float kk  = num[h] / (den + EPS);
        e[h] = __expf(kk * beta_s[h]);
    }

    {
        float4 es = make_float4(e[0], e[1], e[2], e[3]);
        #pragma unroll
        for (int off = 16; off > 0; off >>= 1) {
            es.x += __shfl_xor_sync(0xffffffffu, es.x, off);
            es.y += __shfl_xor_sync(0xffffffffu, es.y, off);
            es.z += __shfl_xor_sync(0xffffffffu, es.z, off);
            es.w += __shfl_xor_sync(0xffffffffu, es.w, off);
        }
        if (lane == 0) red_s[warp] = es;
    }
    __syncthreads();

    float4 t0 = red_s[0], t1 = red_s[1], t2 = red_s[2], t3 = red_s[3];
    float4 t4 = red_s[4], t5 = red_s[5], t6 = red_s[6], t7 = red_s[7];
    float sm[H_DIM];
    sm[0] = 0.5f * (t0.x + t1.x + t2.x + t3.x + t4.x + t5.x + t6.x + t7.x);
    sm[1] = 0.5f * (t0.y + t1.y + t2.y + t3.y + t4.y + t5.y + t6.y + t7.y);
    sm[2] = 0.5f * (t0.z + t1.z + t2.z + t3.z + t4.z + t5.z + t6.z + t7.z);
    sm[3] = 0.5f * (t0.w + t1.w + t2.w + t3.w + t4.w + t5.w + t6.w + t7.w);

    #pragma unroll
    for (int j = 0; j < 2; j++) {
        int h = half * 2 + j;
        out[((size_t)b * H_DIM + h) * M_DIM + m] = e[h] / sm[h];
    }
}

// ---------------------------------------------------------------------------
// Launch
// ---------------------------------------------------------------------------
extern "C" void kernel_launch(void* const* d_in, const int* in_sizes, int n_in,
                              void* d_out, int out_size)
{
    const float* hidden = (const float*)d_in[0];   // [8192, 512]
    const float* memory = (const float*)d_in[1];   // [8192, 128, 64]
    const float* W_key  = (const float*)d_in[2];   // [512, 256]
    const float* b_key  = (const float*)d_in[3];   // [256]
    const float* W_beta = (const float*)d_in[4];   // [512, 4]
    const float* b_beta = (const float*)d_in[5];   // [4]
    float* out = (float*)d_out;                    // [8192, 4, 128]

    float* keybuf;
    cudaGetSymbolAddress((void**)&keybuf, g_key);

    int splitBlocks = (HID4 + WK4 + 255) / 256;
    split_kernel<<<splitBlocks, 256>>>(hidden, W_key);

    dim3 gridA(N_DIM / 128, B_DIM / 128);   // (2, 64) = 128 blocks
    key_gemm_kernel<<<gridA, 256>>>(b_key, keybuf);

    attn_kernel<<<B_DIM, ATT_THREADS, ATT_SMEM>>>(hidden, memory, W_beta,
                                                  b_beta, keybuf, out);
}

// round 9
// speedup vs baseline: 1.7800x; 1.0540x over previous
#include <cuda_runtime.h>
#include <cuda_bf16.h>
#include <mma.h>
#include <math.h>
#include <stdint.h>

using namespace nvcuda;

// Problem constants (fixed shapes)
#define B_DIM 8192
#define D_DIM 512
#define H_DIM 4
#define M_DIM 128
#define W_DIM 64
#define N_DIM (H_DIM * W_DIM)   // 256
#define EPS 1e-6f

// Scratch
__device__ float g_key[(size_t)B_DIM * N_DIM];                    // 8 MB
__device__ __nv_bfloat16 g_ah[(size_t)B_DIM * D_DIM];             // hidden hi
__device__ __nv_bfloat16 g_al[(size_t)B_DIM * D_DIM];             // hidden lo
__device__ __nv_bfloat16 g_wh[(size_t)D_DIM * N_DIM];             // W_key hi
__device__ __nv_bfloat16 g_wl[(size_t)D_DIM * N_DIM];             // W_key lo

// ---------------------------------------------------------------------------
// Kernel 0: split fp32 -> bf16 (hi, lo) for hidden and W_key.
// ---------------------------------------------------------------------------
#define HID4 ((B_DIM * D_DIM) / 4)      // 1,048,576 float4
#define WK4  ((D_DIM * N_DIM) / 4)      // 32,768 float4

__device__ __forceinline__ void split_store(float4 v,
                                            __nv_bfloat16* hi,
                                            __nv_bfloat16* lo,
                                            size_t e)
{
    float x[4] = {v.x, v.y, v.z, v.w};
    __align__(8) __nv_bfloat16 h[4], l[4];
    #pragma unroll
    for (int j = 0; j < 4; j++) {
        h[j] = __float2bfloat16(x[j]);
        l[j] = __float2bfloat16(x[j] - __bfloat162float(h[j]));
    }
    *(uint2*)(hi + e) = *(uint2*)h;
    *(uint2*)(lo + e) = *(uint2*)l;
}

__global__ __launch_bounds__(256)
void split_kernel(const float* __restrict__ hidden,
                  const float* __restrict__ Wk)
{
    int i = blockIdx.x * 256 + threadIdx.x;
    if (i < HID4) {
        float4 v = ((const float4*)hidden)[i];
        split_store(v, g_ah, g_al, (size_t)i * 4);
    } else {
        int j = i - HID4;
        if (j < WK4) {
            float4 v = ((const float4*)Wk)[j];
            split_store(v, g_wh, g_wl, (size_t)j * 4);
        }
    }
}

// ---------------------------------------------------------------------------
// Kernel A: bf16 split-GEMM on tensor cores (wmma m16n16k16).  (round-8 proven)
// key = tanh( Ah@Wh + Ah@Wl + Al@Wh + b )
// ---------------------------------------------------------------------------
#define KB 32
#define APITCH 40
#define BPITCH 136
#define SM_AH 0
#define SM_AL 10240
#define SM_BH 20480
#define SM_BL 29184
#define SM_TOTAL 37888
#define EPI_PITCH 24

__global__ __launch_bounds__(256)
void key_gemm_kernel(const float* __restrict__ bk,     // [256]
                     float* __restrict__ out)          // g_key [B, 256]
{
    __shared__ __align__(16) unsigned char smem_raw[SM_TOTAL];
    __nv_bfloat16* Ah = (__nv_bfloat16*)(smem_raw + SM_AH);
    __nv_bfloat16* Al = (__nv_bfloat16*)(smem_raw + SM_AL);
    __nv_bfloat16* Bh = (__nv_bfloat16*)(smem_raw + SM_BH);
    __nv_bfloat16* Bl = (__nv_bfloat16*)(smem_raw + SM_BL);

    const int tid  = threadIdx.x;
    const int warp = tid >> 5;
    const int lane = tid & 31;
    const int wr   = warp >> 1;
    const int wc   = warp & 1;

    const int row0 = blockIdx.y * 128;
    const int col0 = blockIdx.x * 128;

    const int aF0 = tid, aF1 = tid + 256;
    const int ar0 = aF0 >> 2, ac0 = (aF0 & 3) * 8;
    const int ar1 = aF1 >> 2, ac1 = (aF1 & 3) * 8;
    const int br0 = aF0 >> 4, bc0 = (aF0 & 15) * 8;
    const int br1 = aF1 >> 4, bc1 = (aF1 & 15) * 8;

    wmma::fragment<wmma::accumulator, 16, 16, 16, float> acc[2][4];
    #pragma unroll
    for (int i = 0; i < 2; i++)
        #pragma unroll
        for (int j = 0; j < 4; j++)
            wmma::fill_fragment(acc[i][j], 0.0f);

    #pragma unroll 1
    for (int k0 = 0; k0 < D_DIM; k0 += KB) {
        *(uint4*)&Ah[ar0 * APITCH + ac0] =
            *(const uint4*)&g_ah[(size_t)(row0 + ar0) * D_DIM + k0 + ac0];
        *(uint4*)&Ah[ar1 * APITCH + ac1] =
            *(const uint4*)&g_ah[(size_t)(row0 + ar1) * D_DIM + k0 + ac1];
        *(uint4*)&Al[ar0 * APITCH + ac0] =
            *(const uint4*)&g_al[(size_t)(row0 + ar0) * D_DIM + k0 + ac0];
        *(uint4*)&Al[ar1 * APITCH + ac1] =
            *(const uint4*)&g_al[(size_t)(row0 + ar1) * D_DIM + k0 + ac1];
        *(uint4*)&Bh[br0 * BPITCH + bc0] =
            *(const uint4*)&g_wh[(size_t)(k0 + br0) * N_DIM + col0 + bc0];
        *(uint4*)&Bh[br1 * BPITCH + bc1] =
            *(const uint4*)&g_wh[(size_t)(k0 + br1) * N_DIM + col0 + bc1];
        *(uint4*)&Bl[br0 * BPITCH + bc0] =
            *(const uint4*)&g_wl[(size_t)(k0 + br0) * N_DIM + col0 + bc0];
        *(uint4*)&Bl[br1 * BPITCH + bc1] =
            *(const uint4*)&g_wl[(size_t)(k0 + br1) * N_DIM + col0 + bc1];
        __syncthreads();

        #pragma unroll
        for (int kk = 0; kk < KB; kk += 16) {
            wmma::fragment<wmma::matrix_a, 16, 16, 16, __nv_bfloat16, wmma::row_major> fah[2], fal[2];
            wmma::fragment<wmma::matrix_b, 16, 16, 16, __nv_bfloat16, wmma::row_major> fbh[4], fbl[4];
            #pragma unroll
            for (int i = 0; i < 2; i++) {
                wmma::load_matrix_sync(fah[i], &Ah[(wr * 32 + i * 16) * APITCH + kk], APITCH);
                wmma::load_matrix_sync(fal[i], &Al[(wr * 32 + i * 16) * APITCH + kk], APITCH);
            }
            #pragma unroll
            for (int j = 0; j < 4; j++) {
                wmma::load_matrix_sync(fbh[j], &Bh[kk * BPITCH + wc * 64 + j * 16], BPITCH);
                wmma::load_matrix_sync(fbl[j], &Bl[kk * BPITCH + wc * 64 + j * 16], BPITCH);
            }
            #pragma unroll
            for (int i = 0; i < 2; i++)
                #pragma unroll
                for (int j = 0; j < 4; j++) {
                    wmma::mma_sync(acc[i][j], fah[i], fbh[j], acc[i][j]);
                    wmma::mma_sync(acc[i][j], fah[i], fbl[j], acc[i][j]);
                    wmma::mma_sync(acc[i][j], fal[i], fbh[j], acc[i][j]);
                }
        }
        __syncthreads();
    }

    float* scr = (float*)(smem_raw) + warp * 16 * EPI_PITCH;
    const int er = lane >> 1;
    const int ec = (lane & 1) * 8;

    #pragma unroll
    for (int i = 0; i < 2; i++) {
        #pragma unroll
        for (int j = 0; j < 4; j++) {
            wmma::store_matrix_sync(scr, acc[i][j], EPI_PITCH, wmma::mem_row_major);
            __syncwarp();
            const int gr = row0 + wr * 32 + i * 16 + er;
            const int gc = col0 + wc * 64 + j * 16 + ec;
            float4 c0 = *(float4*)&scr[er * EPI_PITCH + ec];
            float4 c1 = *(float4*)&scr[er * EPI_PITCH + ec + 4];
            float4 b0 = __ldg((const float4*)&bk[gc]);
            float4 b1 = __ldg((const float4*)&bk[gc + 4]);
            float4 o0, o1;
            o0.x = tanhf(c0.x + b0.x); o0.y = tanhf(c0.y + b0.y);
            o0.z = tanhf(c0.z + b0.z); o0.w = tanhf(c0.w + b0.w);
            o1.x = tanhf(c1.x + b1.x); o1.y = tanhf(c1.y + b1.y);
            o1.z = tanhf(c1.z + b1.z); o1.w = tanhf(c1.w + b1.w);
            *(float4*)&out[(size_t)gr * N_DIM + gc]     = o0;
            *(float4*)&out[(size_t)gr * N_DIM + gc + 4] = o1;
            __syncwarp();
        }
    }
}

// ---------------------------------------------------------------------------
// Kernel B: one-shot attention, 256 threads per batch row.
// Tile loaded with ONE cp.async.bulk (TMA path, 32KB, linear layout) into
// dynamic smem + mbarrier. Bank conflicts avoided by a READ-side permutation:
//   ws = (half*8+i) ^ (((m&3)<<1)|half)
// (distinct mod 8 within every quarter-warp), applied to BOTH the tile and
// key indices (dot products are permutation-invariant).
// ---------------------------------------------------------------------------
#define ATT_THREADS 256
#define ATT_SMEM (M_DIM * W_DIM * 4)   // 32768 bytes, linear [128][16] float4

__global__ __launch_bounds__(ATT_THREADS, 6)
void attn_kernel(const float* __restrict__ hidden,   // [B, 512]
                 const float* __restrict__ memory,   // [B, 128, 64]
                 const float* __restrict__ Wb,       // [512, 4]
                 const float* __restrict__ bb,       // [4]
                 const float* __restrict__ key,      // g_key [B, 256]
                 float* __restrict__ out)            // [B, 4, 128]
{
    extern __shared__ float4 tile[];                 // [128][16] linear

    __shared__ float4 key4[N_DIM / 4];
    __shared__ float  u2_s[H_DIM];
    __shared__ float  beta_s[H_DIM];
    __shared__ float4 bpart[4];
    __shared__ float4 red_s[8];
    __shared__ __align__(8) unsigned long long mbar;

    const int b    = blockIdx.x;
    const int tid  = threadIdx.x;
    const int lane = tid & 31;
    const int warp = tid >> 5;
    const int m    = tid >> 1;
    const int half = tid & 1;

    const unsigned int mbar_a =
        (unsigned int)__cvta_generic_to_shared(&mbar);

    // ---- init mbarrier, then fire ONE 32KB bulk copy (TMA path) ----
    if (tid == 0) {
        asm volatile("mbarrier.init.shared.b64 [%0], 1;" :: "r"(mbar_a) : "memory");
        asm volatile("fence.proxy.async.shared::cta;" ::: "memory");
    }
    __syncthreads();
    if (tid == 0) {
        const void* gp = (const void*)&memory[(size_t)b * M_DIM * W_DIM];
        unsigned int dst = (unsigned int)__cvta_generic_to_shared(tile);
        asm volatile("mbarrier.arrive.expect_tx.shared.b64 _, [%0], %1;"
                     :: "r"(mbar_a), "r"(ATT_SMEM) : "memory");
        asm volatile("cp.async.bulk.shared::cta.global.mbarrier::complete_tx::bytes "
                     "[%0], [%1], %2, [%3];"
                     :: "r"(dst), "l"(gp), "r"(ATT_SMEM), "r"(mbar_a) : "memory");
    }

    // ---- overlap with the DMA: beta partials (warps 0-3), key (4-5), u2 (6-7)
    const float4* keyrow4 = (const float4*)&key[(size_t)b * N_DIM];

    if (warp < 4) {
        const float4* h4 = (const float4*)&hidden[(size_t)b * D_DIM];
        float4 hv = h4[warp * 32 + lane];
        const float4* wb4 = (const float4*)Wb;
        int d0 = warp * 128 + lane * 4;
        float4 w0 = wb4[d0 + 0], w1 = wb4[d0 + 1], w2 = wb4[d0 + 2], w3 = wb4[d0 + 3];
        float4 p;
        p.x = hv.x * w0.x + hv.y * w1.x + hv.z * w2.x + hv.w * w3.x;
        p.y = hv.x * w0.y + hv.y * w1.y + hv.z * w2.y + hv.w * w3.y;
        p.z = hv.x * w0.z + hv.y * w1.z + hv.z * w2.z + hv.w * w3.z;
        p.w = hv.x * w0.w + hv.y * w1.w + hv.z * w2.w + hv.w * w3.w;
        #pragma unroll
        for (int off = 16; off > 0; off >>= 1) {
            p.x += __shfl_xor_sync(0xffffffffu, p.x, off);
            p.y += __shfl_xor_sync(0xffffffffu, p.y, off);
            p.z += __shfl_xor_sync(0xffffffffu, p.z, off);
            p.w += __shfl_xor_sync(0xffffffffu, p.w, off);
        }
        if (lane == 0) bpart[warp] = p;
    } else if (warp < 6) {
        int idx = (warp - 4) * 32 + lane;
        key4[idx] = keyrow4[idx];
    } else {
        int idx = (warp - 6) * 32 + lane;
        float4 v = keyrow4[idx];
        float ss = v.x * v.x + v.y * v.y + v.z * v.z + v.w * v.w;
        #pragma unroll
        for (int off = 8; off > 0; off >>= 1)
            ss += __shfl_xor_sync(0xffffffffu, ss, off);
        if ((lane & 15) == 0)
            u2_s[(warp - 6) * 2 + (lane >> 4)] = ss + EPS;
    }

    // wait for the bulk copy (parity 0), then block barrier for key4/u2/bpart
    {
        asm volatile(
            "{\n\t"
            ".reg .pred P;\n"
            "WAIT_%=:\n\t"
            "mbarrier.try_wait.parity.acquire.cta.shared::cta.b64 P, [%0], 0;\n\t"
            "@P bra DONE_%=;\n\t"
            "bra WAIT_%=;\n"
            "DONE_%=:\n\t"
            "}"
            :: "r"(mbar_a) : "memory");
    }
    __syncthreads();

    if (tid < H_DIM) {
        float s = ((const float*)&bpart[0])[tid] + ((const float*)&bpart[1])[tid]
                + ((const float*)&bpart[2])[tid] + ((const float*)&bpart[3])[tid]
                + bb[tid];
        beta_s[tid] = (s > 15.f) ? s : __logf(1.f + __expf(s));
    }

    // ---- dot loop with read-side permutation (conflict-free on linear tile)
    const int perm = ((m & 3) << 1) | half;
    float v2 = 0.f;
    float num[H_DIM] = {0.f, 0.f, 0.f, 0.f};
    #pragma unroll
    for (int i = 0; i < 8; i++) {
        int ws = (half * 8 + i) ^ perm;              // permuted float4 index
        float4 v = tile[m * 16 + ws];
        v2 += v.x * v.x + v.y * v.y + v.z * v.z + v.w * v.w;
        #pragma unroll
        for (int h = 0; h < H_DIM; h++) {
            float4 kh = key4[h * 16 + ws];
            num[h] += kh.x * v.x + kh.y * v.y + kh.z * v.z + kh.w * v.w;
        }
    }
    #pragma unroll
    for (int h = 0; h < H_DIM; h++)
        num[h] += __shfl_xor_sync(0xffffffffu, num[h], 1);
    v2 += __shfl_xor_sync(0xffffffffu, v2, 1);
    v2 += EPS;

    __syncthreads();

    float e[H_DIM];
    #pragma unroll
    for (int h = 0; h < H_DIM; h++) {
        float den = sqrtf(u2_s[h] * v2);
        float kk  = num[h] / (den + EPS);
        e[h] = __expf(kk * beta_s[h]);
    }

    {
        float4 es = make_float4(e[0], e[1], e[2], e[3]);
        #pragma unroll
        for (int off = 16; off > 0; off >>= 1) {
            es.x += __shfl_xor_sync(0xffffffffu, es.x, off);
            es.y += __shfl_xor_sync(0xffffffffu, es.y, off);
            es.z += __shfl_xor_sync(0xffffffffu, es.z, off);
            es.w += __shfl_xor_sync(0xffffffffu, es.w, off);
        }
        if (lane == 0) red_s[warp] = es;
    }
    __syncthreads();

    float4 t0 = red_s[0], t1 = red_s[1], t2 = red_s[2], t3 = red_s[3];
    float4 t4 = red_s[4], t5 = red_s[5], t6 = red_s[6], t7 = red_s[7];
    float sm[H_DIM];
    sm[0] = 0.5f * (t0.x + t1.x + t2.x + t3.x + t4.x + t5.x + t6.x + t7.x);
    sm[1] = 0.5f * (t0.y + t1.y + t2.y + t3.y + t4.y + t5.y + t6.y + t7.y);
    sm[2] = 0.5f * (t0.z + t1.z + t2.z + t3.z + t4.z + t5.z + t6.z + t7.z);
    sm[3] = 0.5f * (t0.w + t1.w + t2.w + t3.w + t4.w + t5.w + t6.w + t7.w);

    #pragma unroll
    for (int j = 0; j < 2; j++) {
        int h = half * 2 + j;
        out[((size_t)b * H_DIM + h) * M_DIM + m] = e[h] / sm[h];
    }
}

// ---------------------------------------------------------------------------
// Launch
// ---------------------------------------------------------------------------
extern "C" void kernel_launch(void* const* d_in, const int* in_sizes, int n_in,
                              void* d_out, int out_size)
{
    const float* hidden = (const float*)d_in[0];   // [8192, 512]
    const float* memory = (const float*)d_in[1];   // [8192, 128, 64]
    const float* W_key  = (const float*)d_in[2];   // [512, 256]
    const float* b_key  = (const float*)d_in[3];   // [256]
    const float* W_beta = (const float*)d_in[4];   // [512, 4]
    const float* b_beta = (const float*)d_in[5];   // [4]
    float* out = (float*)d_out;                    // [8192, 4, 128]

    float* keybuf;
    cudaGetSymbolAddress((void**)&keybuf, g_key);

    int splitBlocks = (HID4 + WK4 + 255) / 256;
    split_kernel<<<splitBlocks, 256>>>(hidden, W_key);

    dim3 gridA(N_DIM / 128, B_DIM / 128);   // (2, 64) = 128 blocks
    key_gemm_kernel<<<gridA, 256>>>(b_key, keybuf);

    attn_kernel<<<B_DIM, ATT_THREADS, ATT_SMEM>>>(hidden, memory, W_beta,
                                                  b_beta, keybuf, out);
}